// round 2
// baseline (speedup 1.0000x reference)
#include <cuda_runtime.h>
#include <math.h>

#define T_DIM 256
#define S_DIM 2048
#define C_DIM 128
#define G3    192
#define L_DIM 64

typedef unsigned long long ull;

// Scratch gx = h_proj @ W_ih^T + b_ih, layout [t][j][s]
__device__ float g_gx[(size_t)T_DIM * G3 * S_DIM];

// ---- packed f32x2 helpers (SASS FFMA2 — 2 MACs per issue slot) ----
__device__ __forceinline__ ull dup2(float x) {
    ull r; asm("mov.b64 %0, {%1, %1};" : "=l"(r) : "f"(x)); return r;
}
__device__ __forceinline__ ull pack2(float x, float y) {
    ull r; asm("mov.b64 %0, {%1, %2};" : "=l"(r) : "f"(x), "f"(y)); return r;
}
__device__ __forceinline__ void fma2(ull& d, ull a, ull b) {
    asm("fma.rn.f32x2 %0, %1, %2, %0;" : "+l"(d) : "l"(a), "l"(b));
}
__device__ __forceinline__ float2 unpk(ull v) {
    float2 f; asm("mov.b64 {%0, %1}, %2;" : "=f"(f.x), "=f"(f.y) : "l"(v)); return f;
}

// ---------------------------------------------------------------------------
// Phase 1: MLP (128->32->64, LeakyReLU) + gx projection (64->192), f32x2.
// 2 blocks/SM (108KB smem). h2 kept in registers (inner k fully unrolled).
// ---------------------------------------------------------------------------
__global__ void __launch_bounds__(256, 2) mlp_gx_kernel(
    const float* __restrict__ x,
    const float* __restrict__ W1, const float* __restrict__ b1,
    const float* __restrict__ W2, const float* __restrict__ b2,
    const float* __restrict__ Wih, const float* __restrict__ bih)
{
    extern __shared__ float sm[];
    float* W1s  = sm;                 // 4096
    float* W2s  = W1s  + 4096;        // 2048
    float* WihT = W2s  + 2048;        // 64*196 = 12544 (16B-aligned rows)
    float* b1s  = WihT + 12544;       // 32
    float* b2s  = b1s  + 32;          // 64
    float* bihs = b2s  + 64;          // 192
    float* h1s  = bihs + 192;         // 32*256 = 8192  [k][tid]
    // total 27168 floats = 108672 B -> 2 blocks/SM

    const int tid = threadIdx.x;

    for (int i = tid; i < 4096; i += 256) W1s[i] = W1[i];
    for (int i = tid; i < 2048; i += 256) W2s[i] = W2[i];
    for (int i = tid; i < 12288; i += 256) {
        int j = i >> 6, k = i & 63;           // Wih is (192,64) row-major
        WihT[k * 196 + j] = Wih[i];
    }
    if (tid < 32)  b1s[tid] = b1[tid];
    if (tid < 64)  b2s[tid] = b2[tid];
    if (tid < 192) bihs[tid] = bih[tid];
    __syncthreads();

    const int row = blockIdx.x * 256 + tid;
    const int t = row >> 11;
    const int s = row & 2047;

    // ---- GEMM1: 128 -> 32 (16 f32x2 accs) ----
    ull a1[16];
    {
        const ull* bp = reinterpret_cast<const ull*>(b1s);
        #pragma unroll
        for (int c = 0; c < 16; c++) a1[c] = bp[c];
    }
    const float4* xv = reinterpret_cast<const float4*>(x + (size_t)row * C_DIM);
    #pragma unroll 4
    for (int k4 = 0; k4 < 32; k4++) {
        float4 xq = __ldg(&xv[k4]);
        float xr[4] = {xq.x, xq.y, xq.z, xq.w};
        #pragma unroll
        for (int kk = 0; kk < 4; kk++) {
            ull xd = dup2(xr[kk]);
            const ulonglong2* w = reinterpret_cast<const ulonglong2*>(&W1s[(k4*4+kk) * 32]);
            #pragma unroll
            for (int c2 = 0; c2 < 8; c2++) {
                ulonglong2 wv = w[c2];
                fma2(a1[c2*2+0], xd, wv.x);
                fma2(a1[c2*2+1], xd, wv.y);
            }
        }
    }
    #pragma unroll
    for (int c = 0; c < 16; c++) {
        float2 f = unpk(a1[c]);
        h1s[(2*c+0) * 256 + tid] = fmaxf(f.x, 0.01f * f.x);
        h1s[(2*c+1) * 256 + tid] = fmaxf(f.y, 0.01f * f.y);
    }

    // ---- GEMM2: 32 -> 64 (32 f32x2 accs) ----
    ull a2[32];
    {
        const ull* bp = reinterpret_cast<const ull*>(b2s);
        #pragma unroll
        for (int c = 0; c < 32; c++) a2[c] = bp[c];
    }
    #pragma unroll 4
    for (int k = 0; k < 32; k++) {
        ull hd = dup2(h1s[k * 256 + tid]);
        const ulonglong2* w = reinterpret_cast<const ulonglong2*>(&W2s[k * 64]);
        #pragma unroll
        for (int c2 = 0; c2 < 16; c2++) {
            ulonglong2 wv = w[c2];
            fma2(a2[c2*2+0], hd, wv.x);
            fma2(a2[c2*2+1], hd, wv.y);
        }
    }
    float h2[64];
    #pragma unroll
    for (int c = 0; c < 32; c++) {
        float2 f = unpk(a2[c]);
        h2[2*c+0] = fmaxf(f.x, 0.01f * f.x);
        h2[2*c+1] = fmaxf(f.y, 0.01f * f.y);
    }

    // ---- GEMM3: 64 -> 192 in 6 chunks of 32 (h2 in regs, k fully unrolled) ----
    float* gbase = &g_gx[(size_t)t * G3 * S_DIM + s];
    #pragma unroll 1
    for (int ch = 0; ch < 6; ch++) {
        const int j0 = ch * 32;
        ull acc[16];
        const ull* bp = reinterpret_cast<const ull*>(&bihs[j0]);
        #pragma unroll
        for (int c = 0; c < 16; c++) acc[c] = bp[c];

        #pragma unroll
        for (int k = 0; k < 64; k++) {
            ull hd = dup2(h2[k]);
            const ulonglong2* w = reinterpret_cast<const ulonglong2*>(&WihT[k * 196 + j0]);
            #pragma unroll
            for (int c2 = 0; c2 < 8; c2++) {
                ulonglong2 wv = w[c2];
                fma2(acc[c2*2+0], hd, wv.x);
                fma2(acc[c2*2+1], hd, wv.y);
            }
        }
        float* gd = gbase + (size_t)j0 * S_DIM;
        #pragma unroll
        for (int c = 0; c < 16; c++) {
            float2 f = unpk(acc[c]);
            gd[(size_t)(2*c+0) * S_DIM] = f.x;
            gd[(size_t)(2*c+1) * S_DIM] = f.y;
        }
    }
}

// ---------------------------------------------------------------------------
// Phase 2: GRU, 128 blocks x 512 threads, 16 stocks/block (16 warps/SM).
// Thread (sg = tid>>5 -> stock, jp = tid&31 -> column pair 2jp,2jp+1).
// All gate GEMM MACs via fma.rn.f32x2; W pairs LDS.64, h warp-broadcast.
// ---------------------------------------------------------------------------
__global__ void __launch_bounds__(512) gru_kernel(
    const float* __restrict__ Whh, const float* __restrict__ bhh,
    float* __restrict__ out)
{
    extern __shared__ float sm[];
    float* WhhT = sm;              // 64*196 = 12544
    float* h_s  = WhhT + 12544;    // 16*64  = 1024   [s][k]
    float* gx_s = h_s + 1024;      // 16*194 = 3104   [s][j] (pad 194)
    // total 16672 floats = 66688 B

    const int tid = threadIdx.x;
    const int jp  = tid & 31;      // column pair index
    const int sg  = tid >> 5;      // stock (one warp per stock)
    const int s0  = blockIdx.x * 16;

    for (int i = tid; i < 12288; i += 512) {
        int j = i >> 6, k = i & 63;           // Whh (192,64) row-major
        WhhT[k * 196 + j] = Whh[j * 64 + k];
    }
    for (int i = tid; i < 1024; i += 512) h_s[i] = 0.0f;

    // Bias pairs hoisted to registers
    ull bb0 = *reinterpret_cast<const ull*>(bhh +       2*jp);
    ull bb1 = *reinterpret_cast<const ull*>(bhh +  64 + 2*jp);
    ull bb2 = *reinterpret_cast<const ull*>(bhh + 128 + 2*jp);
    __syncthreads();

    const ull* w0 = reinterpret_cast<const ull*>(&WhhT[      2*jp]);
    const ull* w1 = reinterpret_cast<const ull*>(&WhhT[ 64 + 2*jp]);
    const ull* w2 = reinterpret_cast<const ull*>(&WhhT[128 + 2*jp]);
    const float4* hrow = reinterpret_cast<const float4*>(&h_s[sg * 64]);

    for (int t = 0; t < T_DIM; t++) {
        // Prefetch this step's gx tile (coalesced; hides HBM under the GEMM)
        float gbuf[6];
        #pragma unroll
        for (int i = 0; i < 6; i++) {
            int idx = tid + 512 * i;
            int j = idx >> 4, ss = idx & 15;
            gbuf[i] = __ldg(&g_gx[((size_t)t * G3 + j) * S_DIM + s0 + ss]);
        }

        // gh = h @ Whh^T + bhh for this stock, column pair, 3 gates
        ull a0 = bb0, a1 = bb1, a2 = bb2;
        #pragma unroll
        for (int k4 = 0; k4 < 16; k4++) {
            float4 hv = hrow[k4];
            float hr[4] = {hv.x, hv.y, hv.z, hv.w};
            #pragma unroll
            for (int kk = 0; kk < 4; kk++) {
                int k = k4 * 4 + kk;
                ull hd = dup2(hr[kk]);
                fma2(a0, hd, w0[k * 98]);
                fma2(a1, hd, w1[k * 98]);
                fma2(a2, hd, w2[k * 98]);
            }
        }

        // Stage gx into shared ([s][j], conflict-free)
        #pragma unroll
        for (int i = 0; i < 6; i++) {
            int idx = tid + 512 * i;
            int j = idx >> 4, ss = idx & 15;
            gx_s[ss * 194 + j] = gbuf[i];
        }
        __syncthreads();   // gx visible; all GEMM reads of old h complete

        // Gates (each thread touches only its own h pair)
        float2 gr = unpk(*reinterpret_cast<const ull*>(&gx_s[sg*194 +       2*jp]));
        float2 gz = unpk(*reinterpret_cast<const ull*>(&gx_s[sg*194 +  64 + 2*jp]));
        float2 gn = unpk(*reinterpret_cast<const ull*>(&gx_s[sg*194 + 128 + 2*jp]));
        float2 ar = unpk(a0), az = unpk(a1), an = unpk(a2);
        float2 hold = unpk(*reinterpret_cast<const ull*>(&h_s[sg*64 + 2*jp]));

        float hn[2];
        #pragma unroll
        for (int e = 0; e < 2; e++) {
            float grv = e ? gr.y : gr.x, gzv = e ? gz.y : gz.x, gnv = e ? gn.y : gn.x;
            float arv = e ? ar.y : ar.x, azv = e ? az.y : az.x, anv = e ? an.y : an.x;
            float hov = e ? hold.y : hold.x;
            float r = 1.0f / (1.0f + __expf(-(grv + arv)));
            float z = 1.0f / (1.0f + __expf(-(gzv + azv)));
            float narg = gnv + r * anv;
            float ex = __expf(-2.0f * fabsf(narg));
            float n = (1.0f - ex) / (1.0f + ex);
            n = copysignf(n, narg);
            hn[e] = (1.0f - z) * n + z * hov;
        }
        *reinterpret_cast<ull*>(&h_s[sg*64 + 2*jp]) = pack2(hn[0], hn[1]);
        __syncthreads();   // new h visible before next step's GEMM
    }

    // Final hidden state, coalesced 8B stores
    ull v = *reinterpret_cast<const ull*>(&h_s[sg*64 + 2*jp]);
    *reinterpret_cast<ull*>(out + (size_t)(s0 + sg) * L_DIM + 2*jp) = v;
}

// ---------------------------------------------------------------------------
extern "C" void kernel_launch(void* const* d_in, const int* in_sizes, int n_in,
                              void* d_out, int out_size)
{
    const float* x   = (const float*)d_in[0];
    const float* W1  = (const float*)d_in[1];
    const float* b1  = (const float*)d_in[2];
    const float* W2  = (const float*)d_in[3];
    const float* b2  = (const float*)d_in[4];
    const float* Wih = (const float*)d_in[5];
    const float* Whh = (const float*)d_in[6];
    const float* bih = (const float*)d_in[7];
    const float* bhh = (const float*)d_in[8];
    float* out = (float*)d_out;

    static bool attrs_set = false;
    if (!attrs_set) {
        cudaFuncSetAttribute(mlp_gx_kernel,
                             cudaFuncAttributeMaxDynamicSharedMemorySize, 27168 * 4);
        cudaFuncSetAttribute(gru_kernel,
                             cudaFuncAttributeMaxDynamicSharedMemorySize, 16672 * 4);
        attrs_set = true;
    }

    mlp_gx_kernel<<<2048, 256, 27168 * 4>>>(x, W1, b1, W2, b2, Wih, bih);
    gru_kernel<<<128, 512, 16672 * 4>>>(Whh, bhh, out);
}

// round 3
// speedup vs baseline: 1.3365x; 1.3365x over previous
#include <cuda_runtime.h>
#include <math.h>

#define T_DIM 256
#define S_DIM 2048
#define C_DIM 128
#define G3    192
#define L_DIM 64

typedef unsigned long long ull;

// Scratch gx = h_proj @ W_ih^T + b_ih, layout [t][j][s]
__device__ float g_gx[(size_t)T_DIM * G3 * S_DIM];

// ---- packed f32x2 helpers ----
__device__ __forceinline__ ull dup2(float x) {
    ull r; asm("mov.b64 %0, {%1, %1};" : "=l"(r) : "f"(x)); return r;
}
__device__ __forceinline__ ull pack2(float x, float y) {
    ull r; asm("mov.b64 %0, {%1, %2};" : "=l"(r) : "f"(x), "f"(y)); return r;
}
__device__ __forceinline__ void fma2(ull& d, ull a, ull b) {
    asm("fma.rn.f32x2 %0, %1, %2, %0;" : "+l"(d) : "l"(a), "l"(b));
}
__device__ __forceinline__ float2 unpk(ull v) {
    float2 f; asm("mov.b64 {%0, %1}, %2;" : "=f"(f.x), "=f"(f.y) : "l"(v)); return f;
}

// ---------------------------------------------------------------------------
// Phase 1: MLP (128->32->64, LeakyReLU) + gx projection (64->192), f32x2.
// (unchanged from R2 — implied ~630us; tensor-core rewrite is the next lever)
// ---------------------------------------------------------------------------
__global__ void __launch_bounds__(256, 2) mlp_gx_kernel(
    const float* __restrict__ x,
    const float* __restrict__ W1, const float* __restrict__ b1,
    const float* __restrict__ W2, const float* __restrict__ b2,
    const float* __restrict__ Wih, const float* __restrict__ bih)
{
    extern __shared__ float sm[];
    float* W1s  = sm;                 // 4096
    float* W2s  = W1s  + 4096;        // 2048
    float* WihT = W2s  + 2048;        // 64*196 = 12544
    float* b1s  = WihT + 12544;       // 32
    float* b2s  = b1s  + 32;          // 64
    float* bihs = b2s  + 64;          // 192
    float* h1s  = bihs + 192;         // 32*256 = 8192  [k][tid]
    // total 27168 floats = 108672 B -> 2 blocks/SM

    const int tid = threadIdx.x;

    for (int i = tid; i < 4096; i += 256) W1s[i] = W1[i];
    for (int i = tid; i < 2048; i += 256) W2s[i] = W2[i];
    for (int i = tid; i < 12288; i += 256) {
        int j = i >> 6, k = i & 63;           // Wih is (192,64) row-major
        WihT[k * 196 + j] = Wih[i];
    }
    if (tid < 32)  b1s[tid] = b1[tid];
    if (tid < 64)  b2s[tid] = b2[tid];
    if (tid < 192) bihs[tid] = bih[tid];
    __syncthreads();

    const int row = blockIdx.x * 256 + tid;
    const int t = row >> 11;
    const int s = row & 2047;

    // ---- GEMM1: 128 -> 32 ----
    ull a1[16];
    {
        const ull* bp = reinterpret_cast<const ull*>(b1s);
        #pragma unroll
        for (int c = 0; c < 16; c++) a1[c] = bp[c];
    }
    const float4* xv = reinterpret_cast<const float4*>(x + (size_t)row * C_DIM);
    #pragma unroll 4
    for (int k4 = 0; k4 < 32; k4++) {
        float4 xq = __ldg(&xv[k4]);
        float xr[4] = {xq.x, xq.y, xq.z, xq.w};
        #pragma unroll
        for (int kk = 0; kk < 4; kk++) {
            ull xd = dup2(xr[kk]);
            const ulonglong2* w = reinterpret_cast<const ulonglong2*>(&W1s[(k4*4+kk) * 32]);
            #pragma unroll
            for (int c2 = 0; c2 < 8; c2++) {
                ulonglong2 wv = w[c2];
                fma2(a1[c2*2+0], xd, wv.x);
                fma2(a1[c2*2+1], xd, wv.y);
            }
        }
    }
    #pragma unroll
    for (int c = 0; c < 16; c++) {
        float2 f = unpk(a1[c]);
        h1s[(2*c+0) * 256 + tid] = fmaxf(f.x, 0.01f * f.x);
        h1s[(2*c+1) * 256 + tid] = fmaxf(f.y, 0.01f * f.y);
    }

    // ---- GEMM2: 32 -> 64 ----
    ull a2[32];
    {
        const ull* bp = reinterpret_cast<const ull*>(b2s);
        #pragma unroll
        for (int c = 0; c < 32; c++) a2[c] = bp[c];
    }
    #pragma unroll 4
    for (int k = 0; k < 32; k++) {
        ull hd = dup2(h1s[k * 256 + tid]);
        const ulonglong2* w = reinterpret_cast<const ulonglong2*>(&W2s[k * 64]);
        #pragma unroll
        for (int c2 = 0; c2 < 16; c2++) {
            ulonglong2 wv = w[c2];
            fma2(a2[c2*2+0], hd, wv.x);
            fma2(a2[c2*2+1], hd, wv.y);
        }
    }
    float h2[64];
    #pragma unroll
    for (int c = 0; c < 32; c++) {
        float2 f = unpk(a2[c]);
        h2[2*c+0] = fmaxf(f.x, 0.01f * f.x);
        h2[2*c+1] = fmaxf(f.y, 0.01f * f.y);
    }

    // ---- GEMM3: 64 -> 192 in 6 chunks of 32 ----
    float* gbase = &g_gx[(size_t)t * G3 * S_DIM + s];
    #pragma unroll 1
    for (int ch = 0; ch < 6; ch++) {
        const int j0 = ch * 32;
        ull acc[16];
        const ull* bp = reinterpret_cast<const ull*>(&bihs[j0]);
        #pragma unroll
        for (int c = 0; c < 16; c++) acc[c] = bp[c];

        #pragma unroll
        for (int k = 0; k < 64; k++) {
            ull hd = dup2(h2[k]);
            const ulonglong2* w = reinterpret_cast<const ulonglong2*>(&WihT[k * 196 + j0]);
            #pragma unroll
            for (int c2 = 0; c2 < 8; c2++) {
                ulonglong2 wv = w[c2];
                fma2(acc[c2*2+0], hd, wv.x);
                fma2(acc[c2*2+1], hd, wv.y);
            }
        }
        float* gd = gbase + (size_t)j0 * S_DIM;
        #pragma unroll
        for (int c = 0; c < 16; c++) {
            float2 f = unpk(acc[c]);
            gd[(size_t)(2*c+0) * S_DIM] = f.x;
            gd[(size_t)(2*c+1) * S_DIM] = f.y;
        }
    }
}

// ---------------------------------------------------------------------------
// Phase 2: GRU. 128 blocks x 384 threads, 16 stocks/block.
// Thread = (gate g, column j, stock-octet sp): tid = (g*64+j)*2 + sp.
// Weights pre-duplicated in 64 registers (NO weight loads in the t-loop).
// f32x2 pairs STOCKS: h stored [k][s] so ulonglong2 LDS feeds fma2 directly
// (no MOV in inner loop). Gates recombined through a small gh smem tile.
// ---------------------------------------------------------------------------
__global__ void __launch_bounds__(384, 1) gru_kernel(
    const float* __restrict__ Whh, const float* __restrict__ bhh,
    float* __restrict__ out)
{
    __shared__ float h_s[64 * 20];     // [k][s], stride 20 (16B-aligned rows)
    __shared__ float gx_s[192 * 18];   // [j][s], stride 18
    __shared__ ull   gh_s[192 * 9];    // [g*64+j][stock-pair], stride 9

    const int tid = threadIdx.x;
    const int sp  = tid & 1;           // stock octet: stocks 8sp..8sp+7
    const int gj  = tid >> 1;          // 0..191 = g*64 + j
    const int s0  = blockIdx.x * 16;

    // Hoist weights into registers, pre-duplicated for f32x2
    ull wreg[64];
    {
        const float4* wp = reinterpret_cast<const float4*>(Whh + (size_t)gj * L_DIM);
        #pragma unroll
        for (int k4 = 0; k4 < 16; k4++) {
            float4 w = __ldg(&wp[k4]);
            wreg[k4*4+0] = dup2(w.x);
            wreg[k4*4+1] = dup2(w.y);
            wreg[k4*4+2] = dup2(w.z);
            wreg[k4*4+3] = dup2(w.w);
        }
    }
    const ull bb = dup2(__ldg(&bhh[gj]));

    for (int i = tid; i < 64 * 20; i += 384) h_s[i] = 0.0f;
    __syncthreads();

    for (int t = 0; t < T_DIM; t++) {
        // Prefetch this step's gx tile (coalesced; hidden under the GEMM)
        float gbuf[8];
        #pragma unroll
        for (int i = 0; i < 8; i++) {
            int idx = tid + 384 * i;              // 3072 = 192*16
            int jj = idx >> 4, ss = idx & 15;
            gbuf[i] = __ldg(&g_gx[((size_t)t * G3 + jj) * S_DIM + s0 + ss]);
        }

        // gh(g, j, stocks 8sp..8sp+7) = sum_k h[k][s] * w[g*64+j][k]
        ull a0 = bb, a1 = bb, a2 = bb, a3 = bb;
        const float* hp = h_s + 8 * sp;
        #pragma unroll
        for (int k = 0; k < 64; k++) {
            ulonglong2 hA = *reinterpret_cast<const ulonglong2*>(hp + k * 20);
            ulonglong2 hB = *reinterpret_cast<const ulonglong2*>(hp + k * 20 + 4);
            fma2(a0, hA.x, wreg[k]);
            fma2(a1, hA.y, wreg[k]);
            fma2(a2, hB.x, wreg[k]);
            fma2(a3, hB.y, wreg[k]);
        }
        {
            ull* ghrow = gh_s + gj * 9 + sp * 4;
            ghrow[0] = a0; ghrow[1] = a1; ghrow[2] = a2; ghrow[3] = a3;
        }

        // Stage gx into shared [j][s]
        #pragma unroll
        for (int i = 0; i < 8; i++) {
            int idx = tid + 384 * i;
            int jj = idx >> 4, ss = idx & 15;
            gx_s[jj * 18 + ss] = gbuf[i];
        }
        __syncthreads();   // gh + gx visible; all GEMM reads of old h done

        // Gate math: element-pair q = (j, stock-pair spg), 512 total
        #pragma unroll
        for (int r = 0; r < 2; r++) {
            int q = tid + r * 384;
            if (q < 512) {
                int spg = q & 7, jq = q >> 3;
                float2 ar = unpk(gh_s[jq * 9 + spg]);
                float2 az = unpk(gh_s[(64 + jq) * 9 + spg]);
                float2 an = unpk(gh_s[(128 + jq) * 9 + spg]);
                float2 gr = unpk(*reinterpret_cast<const ull*>(gx_s + jq * 18 + 2 * spg));
                float2 gz = unpk(*reinterpret_cast<const ull*>(gx_s + (64 + jq) * 18 + 2 * spg));
                float2 gn = unpk(*reinterpret_cast<const ull*>(gx_s + (128 + jq) * 18 + 2 * spg));
                float2 ho = unpk(*reinterpret_cast<const ull*>(h_s + jq * 20 + 2 * spg));

                float hn[2];
                #pragma unroll
                for (int e = 0; e < 2; e++) {
                    float arv = e ? ar.y : ar.x, azv = e ? az.y : az.x, anv = e ? an.y : an.x;
                    float grv = e ? gr.y : gr.x, gzv = e ? gz.y : gz.x, gnv = e ? gn.y : gn.x;
                    float hov = e ? ho.y : ho.x;
                    float rr = 1.0f / (1.0f + __expf(-(grv + arv)));
                    float zz = 1.0f / (1.0f + __expf(-(gzv + azv)));
                    float narg = gnv + rr * anv;
                    float ex = __expf(-2.0f * fabsf(narg));
                    float nn = (1.0f - ex) / (1.0f + ex);
                    nn = copysignf(nn, narg);
                    hn[e] = (1.0f - zz) * nn + zz * hov;
                }
                *reinterpret_cast<ull*>(h_s + jq * 20 + 2 * spg) = pack2(hn[0], hn[1]);
            }
        }
        __syncthreads();   // new h visible before next step's GEMM
    }

    // Final hidden state: out[(s0+s)*64 + j], lanes consecutive in j
    for (int idx = tid; idx < 1024; idx += 384) {
        int jj = idx & 63, ss = idx >> 6;
        out[(size_t)(s0 + ss) * L_DIM + jj] = h_s[jj * 20 + ss];
    }
}

// ---------------------------------------------------------------------------
extern "C" void kernel_launch(void* const* d_in, const int* in_sizes, int n_in,
                              void* d_out, int out_size)
{
    const float* x   = (const float*)d_in[0];
    const float* W1  = (const float*)d_in[1];
    const float* b1  = (const float*)d_in[2];
    const float* W2  = (const float*)d_in[3];
    const float* b2  = (const float*)d_in[4];
    const float* Wih = (const float*)d_in[5];
    const float* Whh = (const float*)d_in[6];
    const float* bih = (const float*)d_in[7];
    const float* bhh = (const float*)d_in[8];
    float* out = (float*)d_out;

    static bool attrs_set = false;
    if (!attrs_set) {
        cudaFuncSetAttribute(mlp_gx_kernel,
                             cudaFuncAttributeMaxDynamicSharedMemorySize, 27168 * 4);
        attrs_set = true;
    }

    mlp_gx_kernel<<<2048, 256, 27168 * 4>>>(x, W1, b1, W2, b2, Wih, bih);
    gru_kernel<<<128, 384>>>(Whh, bhh, out);
}